// round 11
// baseline (speedup 1.0000x reference)
#include <cuda_runtime.h>
#include <math_constants.h>
#include <cstdint>

// Problem: B=128, L=4096, FILTER_SIZE=2, N_QUBITS=4, 10 classes.
// Analytic reduction: expval_k(b,ol) = K_k * g(b,ol),
//   K_k = cos(p_k1)cos(p_k2)cos(p_k3)   (CNOT ring conjugates Z0 -> Z1Z2Z3)
//   g   = cos(x[ol,1]) * cos(x[ol+1,0]) * cos(x[ol+1,1])
// logits[j] = bias[j] + sum_ol g(ol)*(K0*W[2ol,j]+K1*W[2ol+1,j]); softmax.
#define OLP    4096
#define NCLS   10
#define B_SZ   128
#define NT     1024
#define W_F4   20475          // float4 count of W (8190*10 floats)

// Folded, TRANSPOSED weights d_Wp[j*OLP + ol]; column 4095 folds to zero.
__device__ __align__(16) float d_Wp[NCLS * OLP];
// Per-slice publish flags + finish ticket (zero at load; kernel re-zeroes).
__device__ int d_flag[B_SZ];
__device__ int d_fin;

// ---------------------------------------------------------------------------
// Single kernel: 128 co-resident blocks x 1024 threads, one batch row each.
// Block s ALSO folds Wp slice s = columns [32s, 32s+32) and publishes a flag.
// Warp w (any block) consumes only slices 4w..4w+3 -> waits on 4 flags, not
// a full grid barrier. Producers never block => deadlock-free in one wave.
// ---------------------------------------------------------------------------
__global__ __launch_bounds__(NT, 1) void qcnn_one(const float* __restrict__ x,
                                                  const float* __restrict__ params,
                                                  const float* __restrict__ W,
                                                  const float* __restrict__ bias,
                                                  float* __restrict__ out)
{
    __shared__ __align__(16) float sw[640];     // 160 float4 of raw W
    __shared__ float sred[32][NCLS];

    const int b    = blockIdx.x;
    const int tid  = threadIdx.x;
    const int lane = tid & 31;
    const int warp = tid >> 5;

    // ---- issue x loads immediately (DRAM latency drains behind the fold)
    const float* xr = x + (size_t)b * OLP * 2;
    const float4* xr4 = (const float4*)xr;
    float4 v0 = xr4[2 * tid];                   // pairs 4t, 4t+1
    float4 v1 = xr4[2 * tid + 1];               // pairs 4t+2, 4t+3

    // ---- fold this block's slice: Wp columns [32b, 32b+32)
    if (tid < 160) {                            // raw W float4 [160b, 160b+160)
        int gi = 160 * b + tid;
        float4 v = (gi < W_F4) ? ((const float4*)W)[gi]
                               : make_float4(0.f, 0.f, 0.f, 0.f);
        *(float4*)&sw[4 * tid] = v;
    }
    __syncthreads();
    if (tid < 32) {
        float K0 = __cosf(params[1]) * __cosf(params[2]) * __cosf(params[3]);
        float K1 = __cosf(params[5]) * __cosf(params[6]) * __cosf(params[7]);
        int ol = 32 * b + tid;
        const float* r = &sw[20 * tid];         // rows 2ol, 2ol+1 (10 f each)
#pragma unroll
        for (int j = 0; j < NCLS; ++j)          // coalesced 128B STG per class
            d_Wp[j * OLP + ol] = fmaf(K1, r[10 + j], K0 * r[j]);
        __threadfence();                        // make stores device-visible
    }
    __syncthreads();                            // order fences before the flag
    if (tid == 0) atomicExch(&d_flag[b], 1);    // publish slice b

    // ---- overlap: neighbor shuffle + cos while producer blocks fold
    float nx = __shfl_down_sync(0xFFFFFFFFu, v0.x, 1);
    float ny = __shfl_down_sync(0xFFFFFFFFu, v0.y, 1);
    if (lane == 31) {
        int off = (tid == NT - 1) ? 0 : 8 * tid + 8;   // clamp pad (weight=0)
        float2 nb = *(const float2*)(xr + off);
        nx = nb.x; ny = nb.y;
    }
    float s1_0 = __cosf(v0.y);
    float s1_1 = __cosf(v0.w), h1 = __cosf(v0.z) * s1_1;
    float s1_2 = __cosf(v1.y), h2 = __cosf(v1.x) * s1_2;
    float s1_3 = __cosf(v1.w), h3 = __cosf(v1.z) * s1_3;
    float h4   = __cosf(nx)   * __cosf(ny);
    float g0 = s1_0 * h1;
    float g1 = s1_1 * h2;
    float g2 = s1_2 * h3;
    float g3 = s1_3 * h4;                       // padded window: folded w = 0

    // ---- per-warp wait: only the 4 slices this warp reads (blocks 4w..4w+3)
    if (lane < 4) {
        while (atomicAdd(&d_flag[4 * warp + lane], 0) == 0) { }
    }
    __syncwarp();

    // ---- dot with folded weights: 10 coalesced LDG.128 (L2-hot, MLP=10)
    const float4* Wp4 = (const float4*)d_Wp;
    float acc[NCLS];
#pragma unroll
    for (int j = 0; j < NCLS; ++j) {
        float4 w = Wp4[j * (OLP / 4) + tid];
        float a;
        a = g0 * w.x;
        a = fmaf(g1, w.y, a);
        a = fmaf(g2, w.z, a);
        a = fmaf(g3, w.w, a);
        acc[j] = a;
    }

    // ---- reduce 1024 threads -> 10 logits
#pragma unroll
    for (int j = 0; j < NCLS; ++j) {
#pragma unroll
        for (int off = 16; off; off >>= 1)
            acc[j] += __shfl_xor_sync(0xFFFFFFFFu, acc[j], off);
    }
    if (lane == 0) {
#pragma unroll
        for (int j = 0; j < NCLS; ++j) sred[warp][j] = acc[j];
    }
    __syncthreads();                            // all warps past their polls

    // ---- final reduce + softmax in warp 0 (lanes 0..9 own one class)
    if (tid < 32) {
        float logit = -CUDART_INF_F;
        if (tid < NCLS) {
            logit = bias[tid];
#pragma unroll
            for (int w = 0; w < 32; ++w) logit += sred[w][tid];
        }
        float mx = logit;
#pragma unroll
        for (int off = 16; off; off >>= 1)
            mx = fmaxf(mx, __shfl_xor_sync(0xFFFFFFFFu, mx, off));
        float e = (tid < NCLS) ? __expf(logit - mx) : 0.0f;
        float s = e;
#pragma unroll
        for (int off = 16; off; off >>= 1)
            s += __shfl_xor_sync(0xFFFFFFFFu, s, off);
        if (tid < NCLS) out[b * NCLS + tid] = e / s;
    }

    // ---- last block to finish resets flags + ticket (graph-replay safe:
    // reset only runs when all 128 blocks are done => nobody is polling)
    if (tid == 0) {
        if (atomicAdd(&d_fin, 1) == B_SZ - 1) {
#pragma unroll 4
            for (int i = 0; i < B_SZ; ++i) d_flag[i] = 0;
            d_fin = 0;
            __threadfence();
        }
    }
}

// Inputs (metadata order): inputs(128*4096*2 f32), params(8 f32),
//                          W(8190*10 f32), b(10 f32). Output: (128*10) f32.
extern "C" void kernel_launch(void* const* d_in, const int* in_sizes, int n_in,
                              void* d_out, int out_size)
{
    const float* inputs = (const float*)d_in[0];
    const float* params = (const float*)d_in[1];
    const float* W      = (const float*)d_in[2];
    const float* bias   = (const float*)d_in[3];
    float* out          = (float*)d_out;

    qcnn_one<<<B_SZ, NT>>>(inputs, params, W, bias, out);
}